// round 14
// baseline (speedup 1.0000x reference)
#include <cuda_runtime.h>
#include <cuda_fp16.h>
#include <math.h>

#define WD 128
#define FO 6145
#define TP 6400           // t-major padded rows
#define TFULL 8192
#define NL 20

// ---------------- scratch ----------------------------------------------------
__device__ __align__(256) float g_x0[(size_t)8 * WD * TFULL + 2048];
__device__ __align__(256) float g_x1[(size_t)8 * WD * TFULL + 2048];
__device__ __align__(256) unsigned short g_actsH[(size_t)8 * TP * 2560]; // [b][t][l*128+c]
__device__ __align__(256) unsigned short g_skipH[(size_t)8 * TP * 512];  // [b][t][o]
__device__ __align__(256) unsigned short g_hH[(size_t)8 * TP * 512];
__device__ __align__(256) unsigned g_iWd[(size_t)NL * 32768];  // fragment-packed half2
__device__ __align__(256) unsigned g_iWr[(size_t)NL * 8192];
__device__ __align__(256) unsigned g_iWs[655360];
__device__ __align__(256) unsigned g_iP1[131072];
__device__ __align__(256) unsigned g_iP2[65536];

// ---------------- helpers ----------------------------------------------------
__device__ __forceinline__ void mmaf16(float* c, uint4 a, uint2 b) {
    asm volatile("mma.sync.aligned.m16n8k16.row.col.f32.f16.f16.f32 "
                 "{%0,%1,%2,%3},{%4,%5,%6,%7},{%8,%9},{%0,%1,%2,%3};\n"
                 : "+f"(c[0]), "+f"(c[1]), "+f"(c[2]), "+f"(c[3])
                 : "r"(a.x), "r"(a.y), "r"(a.z), "r"(a.w), "r"(b.x), "r"(b.y));
}
__device__ __forceinline__ float tanh_fast(float v) {
    float t; asm("tanh.approx.f32 %0, %1;" : "=f"(t) : "f"(v)); return t;
}
__device__ __forceinline__ void cp16(uint4* dst_smem, const uint4* src) {
    unsigned a = (unsigned)__cvta_generic_to_shared(dst_smem);
    asm volatile("cp.async.cg.shared.global [%0], [%1], 16;" :: "r"(a), "l"(src));
}
#define CP_COMMIT asm volatile("cp.async.commit_group;")
#define CP_WAIT0  asm volatile("cp.async.wait_group 0;")
#define CP_WAIT1  asm volatile("cp.async.wait_group 1;")

// B-fragment half index for element (k, t) in a [k-chunks x 128t] tile
__device__ __forceinline__ int bIdx(int k, int t) {
    int ch = k >> 4, kk = k & 15, tt = t >> 3, gg = t & 7;
    int r = kk >> 3, qq = (kk & 7) >> 1, hh = kk & 1;
    return (((ch * 16 + tt) * 32 + gg * 4 + qq) * 2 + r) * 2 + hh;
}
__device__ __forceinline__ void stB(unsigned* Xs, int k, int t, float v) {
    ((__half*)Xs)[bIdx(k, t)] = __float2half_rn(v);
}

// ---------------- merged weight image prep (ONE launch) ----------------------
// rows 0..19: Wd layer r; rows 20..39: Wr layer r-20; 40: Ws; 41: p1; 42: p2
__global__ void __launch_bounds__(256) prepAll(
    const float* __restrict__ Wd, const float* __restrict__ Wr,
    const float* __restrict__ Ws, const float* __restrict__ p1,
    const float* __restrict__ p2,
    unsigned* __restrict__ iWd, unsigned* __restrict__ iWr,
    unsigned* __restrict__ iWs, unsigned* __restrict__ iP1,
    unsigned* __restrict__ iP2)
{
    int row = blockIdx.y;
    const float* W; unsigned* img; int K, NO;
    if (row < 20)      { W = Wd + (size_t)row * 65536;        img = iWd + (size_t)row * 32768; K = 256;  NO = 256; }
    else if (row < 40) { W = Wr + (size_t)(row - 20) * 16384; img = iWr + (size_t)(row - 20) * 8192; K = 128; NO = 128; }
    else if (row == 40){ W = Ws; img = iWs; K = 2560; NO = 512; }
    else if (row == 41){ W = p1; img = iP1; K = 512;  NO = 512; }
    else               { W = p2; img = iP2; K = 512;  NO = 256; }

    int OTB = (NO >= 256) ? 256 : NO;
    int mtiles = OTB / 16, chunks = K / 16;
    int total = (K * NO) >> 1;
    for (int idx = blockIdx.x * 256 + threadIdx.x; idx < total; idx += gridDim.x * 256) {
        int r = idx & 3, lane = (idx >> 2) & 31;
        int t2 = idx >> 7;
        int mt = t2 % mtiles; t2 /= mtiles;
        int ch = t2 % chunks; int ot = t2 / chunks;
        int m = ot * OTB + mt * 16 + (lane >> 2) + (r & 1) * 8;
        int k0 = ch * 16 + (lane & 3) * 2 + (r >> 1) * 8;
        __half2 h = __floats2half2_rn(W[(size_t)k0 * NO + m], W[(size_t)(k0 + 1) * NO + m]);
        img[idx] = *(unsigned*)&h;
    }
}

// ---------------- embedding ---------------------------------------------------
__global__ void __launch_bounds__(256) embed_kernel(
    const int* __restrict__ y, const float* __restrict__ emb, float* __restrict__ x)
{
    int b = blockIdx.y;
    int t = blockIdx.x * 32 + (threadIdx.x & 31);
    int cg = threadIdx.x >> 5;
    int idx = y[b * TFULL + t];
    const float* er = emb + (size_t)idx * WD;
    float* xb = x + (size_t)b * WD * TFULL;
#pragma unroll
    for (int j = 0; j < 16; ++j) xb[(size_t)(cg * 16 + j) * TFULL + t] = er[cg * 16 + j];
}

// weight-ring stage fill (plain function, no lambda captures)
__device__ __forceinline__ void issueW(
    unsigned* Wr3, const unsigned* iWdl, const unsigned* iWrl, int u, int tid)
{
    uint4* dst = (uint4*)(Wr3 + (u % 3) * 4096);
    if (u < 8) {
        const uint4* src = (const uint4*)(iWdl + u * 4096);
        for (int i = tid; i < 1024; i += 512) cp16(dst + i, src + i);
    } else {
        const uint4* src = (const uint4*)(iWrl + (u - 8) * 2048);
        cp16(dst + tid, src + tid);
    }
    CP_COMMIT;
}

// ---------------- fused per-layer kernel (fp16 mma, 3-deep weight ring) ------
__global__ void __launch_bounds__(512, 1) layer_kernel(
    const float* __restrict__ xin, float* __restrict__ xout,
    const unsigned* __restrict__ iWd, const float* __restrict__ bdl,
    const unsigned* __restrict__ iWr, const float* __restrict__ brl,
    int d, int Lout, int layer)
{
    extern __shared__ unsigned sm[];
    unsigned* Xs = sm;            // 16384 u32: B-fragment tile, 256k x 128t
    unsigned* Wr3 = sm + 16384;   // 3 x 4096 u32: weight ring
    unsigned* Sg = sm + 28672;    // 8192 u32: acts staging [t][c] halfs

    const int tid = threadIdx.x;
    const int w = tid >> 5, lane = tid & 31, g = lane >> 2, q = lane & 3;
    const int b = blockIdx.y;
    const int t0 = blockIdx.x * 128;
    const float* xb = xin + (size_t)b * WD * TFULL;
    const unsigned* iWdl = iWd + (size_t)layer * 32768;
    const unsigned* iWrl = iWr + (size_t)layer * 8192;

    issueW(Wr3, iWdl, iWrl, 0, tid);
    issueW(Wr3, iWdl, iWrl, 1, tid);

    // X tile into B-fragment layout (tap0 rows k 0..127, tap1 rows 128..255)
    for (int i = tid; i < 128 * 32; i += 512) {
        int k = i >> 5, t4 = (i & 31) << 2;
        int tg = t0 + t4; if (tg > TFULL - 4) tg = TFULL - 4;
        float4 v = *(const float4*)(xb + (size_t)k * TFULL + tg);
        stB(Xs, k, t4, v.x); stB(Xs, k, t4 + 1, v.y);
        stB(Xs, k, t4 + 2, v.z); stB(Xs, k, t4 + 3, v.w);
    }
    if ((d & 3) == 0) {
        for (int i = tid; i < 128 * 32; i += 512) {
            int k = i >> 5, t4 = (i & 31) << 2;
            int tg = t0 + t4 + d; if (tg > TFULL - 4) tg = TFULL - 4;
            float4 v = *(const float4*)(xb + (size_t)k * TFULL + tg);
            stB(Xs, 128 + k, t4, v.x); stB(Xs, 128 + k, t4 + 1, v.y);
            stB(Xs, 128 + k, t4 + 2, v.z); stB(Xs, 128 + k, t4 + 3, v.w);
        }
    } else {
        for (int i = tid; i < 128 * 128; i += 512) {
            int k = i >> 7, t = i & 127;
            int tg = t0 + t + d; if (tg > TFULL - 1) tg = TFULL - 1;
            stB(Xs, 128 + k, t, xb[(size_t)k * TFULL + tg]);
        }
    }

    const int m0 = (w & 3) * 64, n0 = (w >> 2) * 32;
    const int mtb = (w & 3) * 4, ntb = n0 >> 3;

    float acc[4][4][4];
#pragma unroll
    for (int mf = 0; mf < 4; ++mf)
#pragma unroll
        for (int nf = 0; nf < 4; ++nf)
#pragma unroll
            for (int e = 0; e < 4; ++e) acc[mf][nf][e] = 0.0f;

    // ---- Phase 1: stages u = 0..7 (k32 each), 2-deep prefetch
    for (int u = 0; u < 8; ++u) {
        CP_WAIT1;
        __syncthreads();
        issueW(Wr3, iWdl, iWrl, u + 2, tid);
        const unsigned* Wst = Wr3 + (u % 3) * 4096;
#pragma unroll
        for (int sub = 0; sub < 2; ++sub) {
            int chAbs = u * 2 + sub;
            uint4 A[4]; uint2 B[4];
#pragma unroll
            for (int mf = 0; mf < 4; ++mf)
                A[mf] = *(const uint4*)(Wst + ((sub * 16 + mtb + mf) * 32 + lane) * 4);
#pragma unroll
            for (int nf = 0; nf < 4; ++nf)
                B[nf] = *(const uint2*)(Xs + ((chAbs * 16 + ntb + nf) * 32 + lane) * 2);
#pragma unroll
            for (int mf = 0; mf < 4; ++mf)
#pragma unroll
                for (int nf = 0; nf < 4; ++nf)
                    mmaf16(acc[mf][nf], A[mf], B[nf]);
        }
    }
    __syncthreads();   // all reads of Xs done before gate overwrites

    // ---- gate: hi warps write sigmoid (half) into acts slots
    if (m0 >= 128) {
#pragma unroll
        for (int mf = 0; mf < 4; ++mf) {
            int r0 = m0 + mf * 16 + g;
            float b0v = bdl[r0], b1v = bdl[r0 + 8];
#pragma unroll
            for (int nf = 0; nf < 4; ++nf) {
                int c0 = n0 + nf * 8 + q * 2;
#pragma unroll
                for (int e = 0; e < 4; ++e) {
                    int row = r0 + ((e >= 2) ? 8 : 0), col = c0 + (e & 1);
                    float v = acc[mf][nf][e] + ((e >= 2) ? b1v : b0v);
                    stB(Xs, row - 128, col, __fdividef(1.0f, 1.0f + __expf(-v)));
                }
            }
        }
    }
    __syncthreads();
    if (m0 < 128) {
#pragma unroll
        for (int mf = 0; mf < 4; ++mf) {
            int r0 = m0 + mf * 16 + g;
            float b0v = bdl[r0], b1v = bdl[r0 + 8];
#pragma unroll
            for (int nf = 0; nf < 4; ++nf) {
                int c0 = n0 + nf * 8 + q * 2;
#pragma unroll
                for (int e = 0; e < 4; ++e) {
                    int row = r0 + ((e >= 2) ? 8 : 0), col = c0 + (e & 1);
                    float v = acc[mf][nf][e] + ((e >= 2) ? b1v : b0v);
                    int hi = bIdx(row, col);
                    float sv = __half2float(((__half*)Xs)[hi]);
                    float av = tanh_fast(v) * sv;
                    ((__half*)Xs)[hi] = __float2half_rn(av);
                    ((__half*)Sg)[col * 128 + row] = __float2half_rn(av);
                }
            }
        }
    }
    __syncthreads();

    // ---- acts tail to g_actsH [b][t][2560] (vectorized from Sg)
    {
        const int tail = Lout - FO;
        if (t0 + 128 > tail) {
            __half* ag = (__half*)g_actsH + (size_t)b * TP * 2560 + layer * 128;
            for (int i = tid; i < 2048; i += 512) {
                int t = i >> 4, seg = i & 15;
                int tg = t0 + t;
                if (tg >= tail && tg < Lout)
                    *(uint4*)(ag + (size_t)(tg - tail) * 2560 + seg * 8) =
                        ((const uint4*)Sg)[t * 16 + seg];
            }
        }
    }

    // ---- Phase 2: stages u = 8..11 (k32 each), same ring
    const int mtb2 = (w & 3) * 2;
    float ac2[2][4][4];
#pragma unroll
    for (int mf = 0; mf < 2; ++mf)
#pragma unroll
        for (int nf = 0; nf < 4; ++nf)
#pragma unroll
            for (int e = 0; e < 4; ++e) ac2[mf][nf][e] = 0.0f;

    for (int u = 8; u < 12; ++u) {
        if (u < 11) { CP_WAIT1; } else { CP_WAIT0; }
        __syncthreads();
        if (u + 2 < 12) issueW(Wr3, iWdl, iWrl, u + 2, tid);
        const unsigned* Wst = Wr3 + (u % 3) * 4096;
        int s2 = u - 8;
#pragma unroll
        for (int sub = 0; sub < 2; ++sub) {
            int chAbs = s2 * 2 + sub;
            uint4 A[2]; uint2 B[4];
#pragma unroll
            for (int mf = 0; mf < 2; ++mf)
                A[mf] = *(const uint4*)(Wst + ((sub * 8 + mtb2 + mf) * 32 + lane) * 4);
#pragma unroll
            for (int nf = 0; nf < 4; ++nf)
                B[nf] = *(const uint2*)(Xs + ((chAbs * 16 + ntb + nf) * 32 + lane) * 2);
#pragma unroll
            for (int mf = 0; mf < 2; ++mf)
#pragma unroll
                for (int nf = 0; nf < 4; ++nf)
                    mmaf16(ac2[mf][nf], A[mf], B[nf]);
        }
    }
    __syncthreads();   // Xs free now; reuse as f32 Rs

    float* Rs = (float*)Xs;
    const int m0b = (w & 3) * 32;
#pragma unroll
    for (int mf = 0; mf < 2; ++mf) {
        int r0 = m0b + mf * 16 + g;
        float br0 = brl[r0], br1 = brl[r0 + 8];
#pragma unroll
        for (int nf = 0; nf < 4; ++nf) {
            int c0 = n0 + nf * 8 + q * 2;
#pragma unroll
            for (int e = 0; e < 4; ++e) {
                int row = r0 + ((e >= 2) ? 8 : 0), col = c0 + (e & 1);
                Rs[row * 128 + col] = ac2[mf][nf][e] + ((e >= 2) ? br1 : br0);
            }
        }
    }
    __syncthreads();

    float* xo = xout + (size_t)b * WD * TFULL;
    for (int i = tid; i < 128 * 128; i += 512) {
        int cc = i >> 7, t = i & 127, tg = t0 + t;
        if (tg < Lout)
            xo[(size_t)cc * TFULL + tg] = Rs[cc * 128 + t] + xb[(size_t)cc * TFULL + tg + d];
    }
}

// ---------------- fp16 GEMM: out[o,t] = sum_k W[k,o]*X[b,t,k] ---------------
// CTA: 256o x 128t, 512 threads, K chunks of 32, 3-deep A/B rings,
// B LDG hoisted above compute, STS after compute.
__global__ void __launch_bounds__(512, 1) gemm_f16(
    const unsigned short* __restrict__ XH, const unsigned* __restrict__ imgA,
    const float* __restrict__ bias, int nbias, int doRelu,
    int K, int NO, void* __restrict__ outp, int tmajor)
{
    extern __shared__ unsigned sm[];
    unsigned* As3 = sm;            // 3 x 4096 u32
    unsigned* Bs3 = sm + 12288;    // 3 x 2048 u32

    const int tid = threadIdx.x;
    const int w = tid >> 5, lane = tid & 31, g = lane >> 2, q = lane & 3;
    const int b = blockIdx.z, ot = blockIdx.y;
    const int t0 = blockIdx.x * 128;
    const int NC = K >> 5, chunks = K >> 4;
    const __half* Xb = (const __half*)XH + (size_t)b * TP * K;
    const unsigned* imgOt = imgA + (size_t)ot * chunks * 2048;

    const int m0 = (w & 3) * 64, n0 = (w >> 2) * 32;
    const int mtb = (w & 3) * 4, ntb = n0 >> 3;

    // B chunk loader: gmem t-major halfs -> fragment layout
    const int bt = tid >> 2, bj = tid & 3;
    const int bsub = bj >> 1, br_ = bj & 1, btt = bt >> 3, bgg = bt & 7;
    const unsigned bbase = ((bsub * 16 + btt) * 32 + bgg * 4) * 2 + br_;

    {
        const uint4* src0 = (const uint4*)(imgOt);
        for (int i = tid; i < 1024; i += 512) cp16((uint4*)As3 + i, src0 + i);
        CP_COMMIT;
        uint4 v0 = *(const uint4*)(Xb + (size_t)(t0 + bt) * K + bj * 8);
        Bs3[bbase] = v0.x; Bs3[bbase + 2] = v0.y; Bs3[bbase + 4] = v0.z; Bs3[bbase + 6] = v0.w;
        const uint4* src1 = (const uint4*)(imgOt + 4096);
        uint4* dst1 = (uint4*)(As3 + 4096);
        for (int i = tid; i < 1024; i += 512) cp16(dst1 + i, src1 + i);
        CP_COMMIT;
        uint4 v1 = *(const uint4*)(Xb + (size_t)(t0 + bt) * K + 32 + bj * 8);
        unsigned* Bd1 = Bs3 + 2048;
        Bd1[bbase] = v1.x; Bd1[bbase + 2] = v1.y; Bd1[bbase + 4] = v1.z; Bd1[bbase + 6] = v1.w;
    }

    float acc[4][4][4];
#pragma unroll
    for (int mf = 0; mf < 4; ++mf)
#pragma unroll
        for (int nf = 0; nf < 4; ++nf)
#pragma unroll
            for (int e = 0; e < 4; ++e) acc[mf][nf][e] = 0.0f;

    for (int c = 0; c < NC; ++c) {
        if (c + 1 < NC) { CP_WAIT1; } else { CP_WAIT0; }
        __syncthreads();
        uint4 vb;
        const bool pend = (c + 2 < NC);
        if (pend) {
            const uint4* src = (const uint4*)(imgOt + (c + 2) * 4096);
            uint4* dst = (uint4*)(As3 + ((c + 2) % 3) * 4096);
            for (int i = tid; i < 1024; i += 512) cp16(dst + i, src + i);
            CP_COMMIT;
            vb = *(const uint4*)(Xb + (size_t)(t0 + bt) * K + (c + 2) * 32 + bj * 8);
        }
        const unsigned* Wst = As3 + (c % 3) * 4096;
        const unsigned* Bst = Bs3 + (c % 3) * 2048;
#pragma unroll
        for (int sub = 0; sub < 2; ++sub) {
            uint4 A[4]; uint2 B[4];
#pragma unroll
            for (int mf = 0; mf < 4; ++mf)
                A[mf] = *(const uint4*)(Wst + ((sub * 16 + mtb + mf) * 32 + lane) * 4);
#pragma unroll
            for (int nf = 0; nf < 4; ++nf)
                B[nf] = *(const uint2*)(Bst + ((sub * 16 + ntb + nf) * 32 + lane) * 2);
#pragma unroll
            for (int mf = 0; mf < 4; ++mf)
#pragma unroll
                for (int nf = 0; nf < 4; ++nf)
                    mmaf16(acc[mf][nf], A[mf], B[nf]);
        }
        if (pend) {
            unsigned* Bd = Bs3 + ((c + 2) % 3) * 2048;
            Bd[bbase] = vb.x; Bd[bbase + 2] = vb.y; Bd[bbase + 4] = vb.z; Bd[bbase + 6] = vb.w;
        }
    }

    // epilogue
#pragma unroll
    for (int mf = 0; mf < 4; ++mf) {
        int r0 = ot * 256 + m0 + mf * 16 + g;
        float bs0 = 0.0f, bs1 = 0.0f;
        for (int i = 0; i < nbias; ++i) {
            bs0 += bias[(size_t)i * NO + r0];
            bs1 += bias[(size_t)i * NO + r0 + 8];
        }
#pragma unroll
        for (int nf = 0; nf < 4; ++nf) {
            int c0 = t0 + n0 + nf * 8 + q * 2;
#pragma unroll
            for (int e = 0; e < 4; ++e) {
                int row = r0 + ((e >= 2) ? 8 : 0);
                int t = c0 + (e & 1);
                float v = acc[mf][nf][e] + ((e >= 2) ? bs1 : bs0);
                if (doRelu) v = fmaxf(v, 0.0f);
                if (tmajor) {
                    ((__half*)outp)[((size_t)b * TP + t) * NO + row] = __float2half_rn(v);
                } else {
                    if (t < FO)
                        ((float*)outp)[((size_t)b * NO + row) * FO + t] = v;
                }
            }
        }
    }
}

// ---------------- host launcher ----------------------------------------------
extern "C" void kernel_launch(void* const* d_in, const int* in_sizes, int n_in,
                              void* d_out, int out_size)
{
    const int*   y   = (const int*)d_in[0];
    const float* emb = (const float*)d_in[1];
    const float* Wd  = (const float*)d_in[2];
    const float* bd  = (const float*)d_in[3];
    const float* Wr  = (const float*)d_in[4];
    const float* br  = (const float*)d_in[5];
    const float* Ws  = (const float*)d_in[6];
    const float* bs  = (const float*)d_in[7];
    const float* p1  = (const float*)d_in[8];
    const float* p2  = (const float*)d_in[9];
    float* out = (float*)d_out;

    static const int dil[NL] = {1, 2, 4, 8, 16, 32, 64, 128, 256, 512,
                                1, 2, 4, 8, 16, 32, 64, 128, 256, 512};

    size_t smemL = (size_t)(16384 + 12288 + 8192) * 4;   // 147456 B
    size_t smemG = (size_t)(12288 + 6144) * 4;           //  73728 B
    cudaFuncSetAttribute(layer_kernel, cudaFuncAttributeMaxDynamicSharedMemorySize, (int)smemL);
    cudaFuncSetAttribute(gemm_f16,     cudaFuncAttributeMaxDynamicSharedMemorySize, (int)smemG);

    float *x0, *x1;
    unsigned short *actsH, *skipH, *hH;
    unsigned *iWd, *iWr, *iWs, *iP1, *iP2;
    cudaGetSymbolAddress((void**)&x0,    g_x0);
    cudaGetSymbolAddress((void**)&x1,    g_x1);
    cudaGetSymbolAddress((void**)&actsH, g_actsH);
    cudaGetSymbolAddress((void**)&skipH, g_skipH);
    cudaGetSymbolAddress((void**)&hH,    g_hH);
    cudaGetSymbolAddress((void**)&iWd,   g_iWd);
    cudaGetSymbolAddress((void**)&iWr,   g_iWr);
    cudaGetSymbolAddress((void**)&iWs,   g_iWs);
    cudaGetSymbolAddress((void**)&iP1,   g_iP1);
    cudaGetSymbolAddress((void**)&iP2,   g_iP2);

    // ONE prep launch (so ncu -s 5 captures layer_kernel, not prep)
    prepAll<<<dim3(128, 43), 256>>>(Wd, Wr, Ws, p1, p2, iWd, iWr, iWs, iP1, iP2);

    embed_kernel<<<dim3(TFULL / 32, 8), 256>>>(y, emb, x0);

    float* xin = x0;
    float* xout = x1;
    int Tin = TFULL;
    for (int i = 0; i < NL; ++i) {
        int d = dil[i];
        int Lout = Tin - d;
        dim3 grid((Lout + 127) / 128, 8);
        layer_kernel<<<grid, 512, smemL>>>(
            xin, xout, iWd, bd + (size_t)i * 2 * WD, iWr, br + (size_t)i * WD,
            d, Lout, i);
        float* tmp = xin; xin = xout; xout = tmp;
        Tin = Lout;
    }

    dim3 g1(TP / 128, 2, 8);
    gemm_f16<<<g1, 512, smemG>>>(actsH, iWs, bs, NL, 1, 2560, 512, skipH, 1);
    gemm_f16<<<g1, 512, smemG>>>(skipH, iP1, nullptr, 0, 1, 512, 512, hH, 1);
    dim3 g3(TP / 128, 1, 8);
    gemm_f16<<<g3, 512, smemG>>>(hH, iP2, nullptr, 0, 0, 512, 256, out, 0);
}

// round 15
// speedup vs baseline: 1.0408x; 1.0408x over previous
#include <cuda_runtime.h>
#include <cuda_fp16.h>
#include <math.h>

#define WD 128
#define FO 6145
#define TP 6400           // t-major padded rows
#define TFULL 8192
#define NL 20

// ---------------- scratch ----------------------------------------------------
__device__ __align__(256) float g_x0[(size_t)8 * WD * TFULL + 2048];
__device__ __align__(256) float g_x1[(size_t)8 * WD * TFULL + 2048];
__device__ __align__(256) unsigned short g_actsH[(size_t)8 * TP * 2560]; // [b][t][l*128+c]
__device__ __align__(256) unsigned short g_skipH[(size_t)8 * TP * 512];  // [b][t][o]
__device__ __align__(256) unsigned short g_hH[(size_t)8 * TP * 512];
__device__ __align__(256) unsigned g_iWd[(size_t)NL * 32768];  // fragment-packed half2
__device__ __align__(256) unsigned g_iWr[(size_t)NL * 8192];
__device__ __align__(256) unsigned g_iWs[655360];
__device__ __align__(256) unsigned g_iP1[131072];
__device__ __align__(256) unsigned g_iP2[65536];

// ---------------- helpers ----------------------------------------------------
__device__ __forceinline__ void mmaf16(float* c, uint4 a, uint2 b) {
    asm volatile("mma.sync.aligned.m16n8k16.row.col.f32.f16.f16.f32 "
                 "{%0,%1,%2,%3},{%4,%5,%6,%7},{%8,%9},{%0,%1,%2,%3};\n"
                 : "+f"(c[0]), "+f"(c[1]), "+f"(c[2]), "+f"(c[3])
                 : "r"(a.x), "r"(a.y), "r"(a.z), "r"(a.w), "r"(b.x), "r"(b.y));
}
__device__ __forceinline__ float tanh_fast(float v) {
    float t; asm("tanh.approx.f32 %0, %1;" : "=f"(t) : "f"(v)); return t;
}
__device__ __forceinline__ void cp16(uint4* dst_smem, const uint4* src) {
    unsigned a = (unsigned)__cvta_generic_to_shared(dst_smem);
    asm volatile("cp.async.cg.shared.global [%0], [%1], 16;" :: "r"(a), "l"(src));
}
#define CP_COMMIT asm volatile("cp.async.commit_group;")
#define CP_WAIT0  asm volatile("cp.async.wait_group 0;")
#define CP_WAIT1  asm volatile("cp.async.wait_group 1;")

// B-fragment half index for element (k, t) in a [k-chunks x 128t] tile
__device__ __forceinline__ int bIdx(int k, int t) {
    int ch = k >> 4, kk = k & 15, tt = t >> 3, gg = t & 7;
    int r = kk >> 3, qq = (kk & 7) >> 1, hh = kk & 1;
    return (((ch * 16 + tt) * 32 + gg * 4 + qq) * 2 + r) * 2 + hh;
}
__device__ __forceinline__ void stB(unsigned* Xs, int k, int t, float v) {
    ((__half*)Xs)[bIdx(k, t)] = __float2half_rn(v);
}

// ---------------- merged weight image prep (ONE launch) ----------------------
__global__ void __launch_bounds__(256) prepAll(
    const float* __restrict__ Wd, const float* __restrict__ Wr,
    const float* __restrict__ Ws, const float* __restrict__ p1,
    const float* __restrict__ p2,
    unsigned* __restrict__ iWd, unsigned* __restrict__ iWr,
    unsigned* __restrict__ iWs, unsigned* __restrict__ iP1,
    unsigned* __restrict__ iP2)
{
    int row = blockIdx.y;
    const float* W; unsigned* img; int K, NO;
    if (row < 20)      { W = Wd + (size_t)row * 65536;        img = iWd + (size_t)row * 32768; K = 256;  NO = 256; }
    else if (row < 40) { W = Wr + (size_t)(row - 20) * 16384; img = iWr + (size_t)(row - 20) * 8192; K = 128; NO = 128; }
    else if (row == 40){ W = Ws; img = iWs; K = 2560; NO = 512; }
    else if (row == 41){ W = p1; img = iP1; K = 512;  NO = 512; }
    else               { W = p2; img = iP2; K = 512;  NO = 256; }

    int OTB = (NO >= 256) ? 256 : NO;
    int mtiles = OTB / 16, chunks = K / 16;
    int total = (K * NO) >> 1;
    for (int idx = blockIdx.x * 256 + threadIdx.x; idx < total; idx += gridDim.x * 256) {
        int r = idx & 3, lane = (idx >> 2) & 31;
        int t2 = idx >> 7;
        int mt = t2 % mtiles; t2 /= mtiles;
        int ch = t2 % chunks; int ot = t2 / chunks;
        int m = ot * OTB + mt * 16 + (lane >> 2) + (r & 1) * 8;
        int k0 = ch * 16 + (lane & 3) * 2 + (r >> 1) * 8;
        __half2 h = __floats2half2_rn(W[(size_t)k0 * NO + m], W[(size_t)(k0 + 1) * NO + m]);
        img[idx] = *(unsigned*)&h;
    }
}

// ---------------- embedding ---------------------------------------------------
__global__ void __launch_bounds__(256) embed_kernel(
    const int* __restrict__ y, const float* __restrict__ emb, float* __restrict__ x)
{
    int b = blockIdx.y;
    int t = blockIdx.x * 32 + (threadIdx.x & 31);
    int cg = threadIdx.x >> 5;
    int idx = y[b * TFULL + t];
    const float* er = emb + (size_t)idx * WD;
    float* xb = x + (size_t)b * WD * TFULL;
#pragma unroll
    for (int j = 0; j < 16; ++j) xb[(size_t)(cg * 16 + j) * TFULL + t] = er[cg * 16 + j];
}

// weight-ring stage fill: stages 0..3 = Wd 32KB quarters; stage 4 = Wr (32KB)
__device__ __forceinline__ void issueW(
    unsigned* Wr3, const unsigned* iWdl, const unsigned* iWrl, int u, int tid)
{
    uint4* dst = (uint4*)(Wr3 + (u % 3) * 8192);
    const uint4* src = (u < 4) ? (const uint4*)(iWdl + u * 8192)
                               : (const uint4*)iWrl;
    for (int i = tid; i < 2048; i += 512) cp16(dst + i, src + i);
    CP_COMMIT;
}

// ---------------- fused per-layer kernel (fp16 mma, k128 stages) -------------
__global__ void __launch_bounds__(512, 1) layer_kernel(
    const float* __restrict__ xin, float* __restrict__ xout,
    const unsigned* __restrict__ iWd, const float* __restrict__ bdl,
    const unsigned* __restrict__ iWr, const float* __restrict__ brl,
    int d, int Lout, int layer)
{
    extern __shared__ unsigned sm[];
    unsigned* Xs = sm;            // 16384 u32: B-fragment tile, 256k x 128t
    unsigned* Wr3 = sm + 16384;   // 3 x 8192 u32: weight ring (32KB slots)

    const int tid = threadIdx.x;
    const int w = tid >> 5, lane = tid & 31, g = lane >> 2, q = lane & 3;
    const int b = blockIdx.y;
    const int t0 = blockIdx.x * 128;
    const float* xb = xin + (size_t)b * WD * TFULL;
    const unsigned* iWdl = iWd + (size_t)layer * 32768;
    const unsigned* iWrl = iWr + (size_t)layer * 8192;

    issueW(Wr3, iWdl, iWrl, 0, tid);
    issueW(Wr3, iWdl, iWrl, 1, tid);

    // X tile into B-fragment layout (tap0 rows k 0..127, tap1 rows 128..255)
    for (int i = tid; i < 128 * 32; i += 512) {
        int k = i >> 5, t4 = (i & 31) << 2;
        int tg = t0 + t4; if (tg > TFULL - 4) tg = TFULL - 4;
        float4 v = *(const float4*)(xb + (size_t)k * TFULL + tg);
        stB(Xs, k, t4, v.x); stB(Xs, k, t4 + 1, v.y);
        stB(Xs, k, t4 + 2, v.z); stB(Xs, k, t4 + 3, v.w);
    }
    if ((d & 3) == 0) {
        for (int i = tid; i < 128 * 32; i += 512) {
            int k = i >> 5, t4 = (i & 31) << 2;
            int tg = t0 + t4 + d; if (tg > TFULL - 4) tg = TFULL - 4;
            float4 v = *(const float4*)(xb + (size_t)k * TFULL + tg);
            stB(Xs, 128 + k, t4, v.x); stB(Xs, 128 + k, t4 + 1, v.y);
            stB(Xs, 128 + k, t4 + 2, v.z); stB(Xs, 128 + k, t4 + 3, v.w);
        }
    } else {
        for (int i = tid; i < 128 * 128; i += 512) {
            int k = i >> 7, t = i & 127;
            int tg = t0 + t + d; if (tg > TFULL - 1) tg = TFULL - 1;
            stB(Xs, 128 + k, t, xb[(size_t)k * TFULL + tg]);
        }
    }

    const int m0 = (w & 3) * 64, n0 = (w >> 2) * 32;
    const int mtb = (w & 3) * 4, ntb = n0 >> 3;

    float acc[4][4][4];
#pragma unroll
    for (int mf = 0; mf < 4; ++mf)
#pragma unroll
        for (int nf = 0; nf < 4; ++nf)
#pragma unroll
            for (int e = 0; e < 4; ++e) acc[mf][nf][e] = 0.0f;

    // ---- Phase 1: 4 stages of k64 (slot = 32KB = 2 k32 chunks)
    for (int u = 0; u < 4; ++u) {
        CP_WAIT1;
        __syncthreads();
        if (u + 2 <= 4) issueW(Wr3, iWdl, iWrl, u + 2, tid);
        const unsigned* Wst = Wr3 + (u % 3) * 8192;
        for (int sp = 0; sp < 2; ++sp) {
#pragma unroll
            for (int s2 = 0; s2 < 2; ++s2) {
                int sub = sp * 2 + s2;
                int chAbs = u * 4 + sub;
                const unsigned* Wc = Wst + (sub >> 1) * 4096;
                uint4 A[4]; uint2 B[4];
#pragma unroll
                for (int mf = 0; mf < 4; ++mf)
                    A[mf] = *(const uint4*)(Wc + (((sub & 1) * 16 + mtb + mf) * 32 + lane) * 4);
#pragma unroll
                for (int nf = 0; nf < 4; ++nf)
                    B[nf] = *(const uint2*)(Xs + ((chAbs * 16 + ntb + nf) * 32 + lane) * 2);
#pragma unroll
                for (int mf = 0; mf < 4; ++mf)
#pragma unroll
                    for (int nf = 0; nf < 4; ++nf)
                        mmaf16(acc[mf][nf], A[mf], B[nf]);
            }
        }
    }
    __syncthreads();   // all reads of Xs done before gate overwrites

    // ---- gate: hi warps write sigmoid (half) into acts slots
    if (m0 >= 128) {
#pragma unroll
        for (int mf = 0; mf < 4; ++mf) {
            int r0 = m0 + mf * 16 + g;
            float b0v = bdl[r0], b1v = bdl[r0 + 8];
#pragma unroll
            for (int nf = 0; nf < 4; ++nf) {
                int c0 = n0 + nf * 8 + q * 2;
#pragma unroll
                for (int e = 0; e < 4; ++e) {
                    int row = r0 + ((e >= 2) ? 8 : 0), col = c0 + (e & 1);
                    float v = acc[mf][nf][e] + ((e >= 2) ? b1v : b0v);
                    stB(Xs, row - 128, col, __fdividef(1.0f, 1.0f + __expf(-v)));
                }
            }
        }
    }
    __syncthreads();
    if (m0 < 128) {
#pragma unroll
        for (int mf = 0; mf < 4; ++mf) {
            int r0 = m0 + mf * 16 + g;
            float b0v = bdl[r0], b1v = bdl[r0 + 8];
#pragma unroll
            for (int nf = 0; nf < 4; ++nf) {
                int c0 = n0 + nf * 8 + q * 2;
#pragma unroll
                for (int e = 0; e < 4; ++e) {
                    int row = r0 + ((e >= 2) ? 8 : 0), col = c0 + (e & 1);
                    float v = acc[mf][nf][e] + ((e >= 2) ? b1v : b0v);
                    int hi = bIdx(row, col);
                    float sv = __half2float(((__half*)Xs)[hi]);
                    float av = tanh_fast(v) * sv;
                    ((__half*)Xs)[hi] = __float2half_rn(av);
                }
            }
        }
    }
    __syncthreads();

    // ---- acts tail: read fragment layout directly, permute to c-sequential
    {
        const int tail = Lout - FO;
        if (t0 + 128 > tail) {
            __half* ag = (__half*)g_actsH + (size_t)b * TP * 2560 + layer * 128;
            for (int i = tid; i < 1024; i += 512) {
                int t = i >> 3, ch = i & 7;
                int tg = t0 + t;
                if (tg >= tail && tg < Lout) {
                    int tt = t >> 3, gg = t & 7;
                    const uint4* src = (const uint4*)(Xs + (ch * 16 + tt) * 64 + gg * 8);
                    uint4 lo = src[0], hi = src[1];
                    uint4 o0 = make_uint4(lo.x, lo.z, hi.x, hi.z);   // c 0..7
                    uint4 o1 = make_uint4(lo.y, lo.w, hi.y, hi.w);   // c 8..15
                    *(uint4*)(ag + (size_t)(tg - tail) * 2560 + ch * 16) = o0;
                    *(uint4*)(ag + (size_t)(tg - tail) * 2560 + ch * 16 + 8) = o1;
                }
            }
        }
    }

    // ---- Phase 2: Wr fully staged in slot 1 (stage 4); ONE wait + sync
    const int mtb2 = (w & 3) * 2;
    float ac2[2][4][4];
#pragma unroll
    for (int mf = 0; mf < 2; ++mf)
#pragma unroll
        for (int nf = 0; nf < 4; ++nf)
#pragma unroll
            for (int e = 0; e < 4; ++e) ac2[mf][nf][e] = 0.0f;

    CP_WAIT0;
    __syncthreads();
    {
        const unsigned* Wst2 = Wr3 + (4 % 3) * 8192;
        for (int sp = 0; sp < 4; ++sp) {
#pragma unroll
            for (int s2 = 0; s2 < 2; ++s2) {
                int sub = sp * 2 + s2;               // 0..7 = k16 chunk index
                const unsigned* Wc = Wst2 + (sub >> 1) * 2048;
                uint4 A[2]; uint2 B[4];
#pragma unroll
                for (int mf = 0; mf < 2; ++mf)
                    A[mf] = *(const uint4*)(Wc + (((sub & 1) * 8 + mtb2 + mf) * 32 + lane) * 4);
#pragma unroll
                for (int nf = 0; nf < 4; ++nf)
                    B[nf] = *(const uint2*)(Xs + ((sub * 16 + ntb + nf) * 32 + lane) * 2);
#pragma unroll
                for (int mf = 0; mf < 2; ++mf)
#pragma unroll
                    for (int nf = 0; nf < 4; ++nf)
                        mmaf16(ac2[mf][nf], A[mf], B[nf]);
            }
        }
    }
    __syncthreads();   // Xs free now; reuse as f32 Rs

    float* Rs = (float*)Xs;
    const int m0b = (w & 3) * 32;
#pragma unroll
    for (int mf = 0; mf < 2; ++mf) {
        int r0 = m0b + mf * 16 + g;
        float br0 = brl[r0], br1 = brl[r0 + 8];
#pragma unroll
        for (int nf = 0; nf < 4; ++nf) {
            int c0 = n0 + nf * 8 + q * 2;
#pragma unroll
            for (int e = 0; e < 4; ++e) {
                int row = r0 + ((e >= 2) ? 8 : 0), col = c0 + (e & 1);
                Rs[row * 128 + col] = ac2[mf][nf][e] + ((e >= 2) ? br1 : br0);
            }
        }
    }
    __syncthreads();

    float* xo = xout + (size_t)b * WD * TFULL;
    if (((d & 3) == 0) && (t0 + 128 <= Lout)) {
        for (int i = tid; i < 128 * 32; i += 512) {
            int cc = i >> 5, t4 = (i & 31) << 2;
            float4 r4 = *(float4*)(Rs + cc * 128 + t4);
            float4 x4 = *(const float4*)(xb + (size_t)cc * TFULL + t0 + t4 + d);
            float4 o;
            o.x = r4.x + x4.x; o.y = r4.y + x4.y;
            o.z = r4.z + x4.z; o.w = r4.w + x4.w;
            *(float4*)(xo + (size_t)cc * TFULL + t0 + t4) = o;
        }
    } else {
        for (int i = tid; i < 128 * 128; i += 512) {
            int cc = i >> 7, t = i & 127, tg = t0 + t;
            if (tg < Lout)
                xo[(size_t)cc * TFULL + tg] = Rs[cc * 128 + t] + xb[(size_t)cc * TFULL + tg + d];
        }
    }
}

// ---------------- fp16 GEMM: out[o,t] = sum_k W[k,o]*X[b,t,k] ---------------
__global__ void __launch_bounds__(512, 1) gemm_f16(
    const unsigned short* __restrict__ XH, const unsigned* __restrict__ imgA,
    const float* __restrict__ bias, int nbias, int doRelu,
    int K, int NO, void* __restrict__ outp, int tmajor)
{
    extern __shared__ unsigned sm[];
    unsigned* As3 = sm;            // 3 x 4096 u32
    unsigned* Bs3 = sm + 12288;    // 3 x 2048 u32

    const int tid = threadIdx.x;
    const int w = tid >> 5, lane = tid & 31, g = lane >> 2, q = lane & 3;
    const int b = blockIdx.z, ot = blockIdx.y;
    const int t0 = blockIdx.x * 128;
    const int NC = K >> 5, chunks = K >> 4;
    const __half* Xb = (const __half*)XH + (size_t)b * TP * K;
    const unsigned* imgOt = imgA + (size_t)ot * chunks * 2048;

    const int m0 = (w & 3) * 64, n0 = (w >> 2) * 32;
    const int mtb = (w & 3) * 4, ntb = n0 >> 3;

    const int bt = tid >> 2, bj = tid & 3;
    const int bsub = bj >> 1, br_ = bj & 1, btt = bt >> 3, bgg = bt & 7;
    const unsigned bbase = ((bsub * 16 + btt) * 32 + bgg * 4) * 2 + br_;

    {
        const uint4* src0 = (const uint4*)(imgOt);
        for (int i = tid; i < 1024; i += 512) cp16((uint4*)As3 + i, src0 + i);
        CP_COMMIT;
        uint4 v0 = *(const uint4*)(Xb + (size_t)(t0 + bt) * K + bj * 8);
        Bs3[bbase] = v0.x; Bs3[bbase + 2] = v0.y; Bs3[bbase + 4] = v0.z; Bs3[bbase + 6] = v0.w;
        const uint4* src1 = (const uint4*)(imgOt + 4096);
        uint4* dst1 = (uint4*)(As3 + 4096);
        for (int i = tid; i < 1024; i += 512) cp16(dst1 + i, src1 + i);
        CP_COMMIT;
        uint4 v1 = *(const uint4*)(Xb + (size_t)(t0 + bt) * K + 32 + bj * 8);
        unsigned* Bd1 = Bs3 + 2048;
        Bd1[bbase] = v1.x; Bd1[bbase + 2] = v1.y; Bd1[bbase + 4] = v1.z; Bd1[bbase + 6] = v1.w;
    }

    float acc[4][4][4];
#pragma unroll
    for (int mf = 0; mf < 4; ++mf)
#pragma unroll
        for (int nf = 0; nf < 4; ++nf)
#pragma unroll
            for (int e = 0; e < 4; ++e) acc[mf][nf][e] = 0.0f;

    for (int c = 0; c < NC; ++c) {
        if (c + 1 < NC) { CP_WAIT1; } else { CP_WAIT0; }
        __syncthreads();
        uint4 vb;
        const bool pend = (c + 2 < NC);
        if (pend) {
            const uint4* src = (const uint4*)(imgOt + (c + 2) * 4096);
            uint4* dst = (uint4*)(As3 + ((c + 2) % 3) * 4096);
            for (int i = tid; i < 1024; i += 512) cp16(dst + i, src + i);
            CP_COMMIT;
            vb = *(const uint4*)(Xb + (size_t)(t0 + bt) * K + (c + 2) * 32 + bj * 8);
        }
        const unsigned* Wst = As3 + (c % 3) * 4096;
        const unsigned* Bst = Bs3 + (c % 3) * 2048;
#pragma unroll
        for (int sub = 0; sub < 2; ++sub) {
            uint4 A[4]; uint2 B[4];
#pragma unroll
            for (int mf = 0; mf < 4; ++mf)
                A[mf] = *(const uint4*)(Wst + ((sub * 16 + mtb + mf) * 32 + lane) * 4);
#pragma unroll
            for (int nf = 0; nf < 4; ++nf)
                B[nf] = *(const uint2*)(Bst + ((sub * 16 + ntb + nf) * 32 + lane) * 2);
#pragma unroll
            for (int mf = 0; mf < 4; ++mf)
#pragma unroll
                for (int nf = 0; nf < 4; ++nf)
                    mmaf16(acc[mf][nf], A[mf], B[nf]);
        }
        if (pend) {
            unsigned* Bd = Bs3 + ((c + 2) % 3) * 2048;
            Bd[bbase] = vb.x; Bd[bbase + 2] = vb.y; Bd[bbase + 4] = vb.z; Bd[bbase + 6] = vb.w;
        }
    }

    // epilogue
#pragma unroll
    for (int mf = 0; mf < 4; ++mf) {
        int r0 = ot * 256 + m0 + mf * 16 + g;
        float bs0 = 0.0f, bs1 = 0.0f;
        for (int i = 0; i < nbias; ++i) {
            bs0 += bias[(size_t)i * NO + r0];
            bs1 += bias[(size_t)i * NO + r0 + 8];
        }
#pragma unroll
        for (int nf = 0; nf < 4; ++nf) {
            int c0 = t0 + n0 + nf * 8 + q * 2;
#pragma unroll
            for (int e = 0; e < 4; ++e) {
                int row = r0 + ((e >= 2) ? 8 : 0);
                int t = c0 + (e & 1);
                float v = acc[mf][nf][e] + ((e >= 2) ? bs1 : bs0);
                if (doRelu) v = fmaxf(v, 0.0f);
                if (tmajor) {
                    ((__half*)outp)[((size_t)b * TP + t) * NO + row] = __float2half_rn(v);
                } else {
                    if (t < FO)
                        ((float*)outp)[((size_t)b * NO + row) * FO + t] = v;
                }
            }
        }
    }
}

// ---------------- host launcher ----------------------------------------------
extern "C" void kernel_launch(void* const* d_in, const int* in_sizes, int n_in,
                              void* d_out, int out_size)
{
    const int*   y   = (const int*)d_in[0];
    const float* emb = (const float*)d_in[1];
    const float* Wd  = (const float*)d_in[2];
    const float* bd  = (const float*)d_in[3];
    const float* Wr  = (const float*)d_in[4];
    const float* br  = (const float*)d_in[5];
    const float* Ws  = (const float*)d_in[6];
    const float* bs  = (const float*)d_in[7];
    const float* p1  = (const float*)d_in[8];
    const float* p2  = (const float*)d_in[9];
    float* out = (float*)d_out;

    static const int dil[NL] = {1, 2, 4, 8, 16, 32, 64, 128, 256, 512,
                                1, 2, 4, 8, 16, 32, 64, 128, 256, 512};

    size_t smemL = (size_t)(16384 + 3 * 8192) * 4;       // 163,840 B
    size_t smemG = (size_t)(12288 + 6144) * 4;           //  73,728 B
    cudaFuncSetAttribute(layer_kernel, cudaFuncAttributeMaxDynamicSharedMemorySize, (int)smemL);
    cudaFuncSetAttribute(gemm_f16,     cudaFuncAttributeMaxDynamicSharedMemorySize, (int)smemG);

    float *x0, *x1;
    unsigned short *actsH, *skipH, *hH;
    unsigned *iWd, *iWr, *iWs, *iP1, *iP2;
    cudaGetSymbolAddress((void**)&x0,    g_x0);
    cudaGetSymbolAddress((void**)&x1,    g_x1);
    cudaGetSymbolAddress((void**)&actsH, g_actsH);
    cudaGetSymbolAddress((void**)&skipH, g_skipH);
    cudaGetSymbolAddress((void**)&hH,    g_hH);
    cudaGetSymbolAddress((void**)&iWd,   g_iWd);
    cudaGetSymbolAddress((void**)&iWr,   g_iWr);
    cudaGetSymbolAddress((void**)&iWs,   g_iWs);
    cudaGetSymbolAddress((void**)&iP1,   g_iP1);
    cudaGetSymbolAddress((void**)&iP2,   g_iP2);

    prepAll<<<dim3(128, 43), 256>>>(Wd, Wr, Ws, p1, p2, iWd, iWr, iWs, iP1, iP2);

    embed_kernel<<<dim3(TFULL / 32, 8), 256>>>(y, emb, x0);

    float* xin = x0;
    float* xout = x1;
    int Tin = TFULL;
    for (int i = 0; i < NL; ++i) {
        int d = dil[i];
        int Lout = Tin - d;
        dim3 grid((Lout + 127) / 128, 8);
        layer_kernel<<<grid, 512, smemL>>>(
            xin, xout, iWd, bd + (size_t)i * 2 * WD, iWr, br + (size_t)i * WD,
            d, Lout, i);
        float* tmp = xin; xin = xout; xout = tmp;
        Tin = Lout;
    }

    dim3 g1(TP / 128, 2, 8);
    gemm_f16<<<g1, 512, smemG>>>(actsH, iWs, bs, NL, 1, 2560, 512, skipH, 1);
    gemm_f16<<<g1, 512, smemG>>>(skipH, iP1, nullptr, 0, 1, 512, 512, hH, 1);
    dim3 g3(TP / 128, 1, 8);
    gemm_f16<<<g3, 512, smemG>>>(hH, iP2, nullptr, 0, 0, 512, 256, out, 0);
}

// round 16
// speedup vs baseline: 1.6260x; 1.5624x over previous
#include <cuda_runtime.h>
#include <cuda_fp16.h>
#include <math.h>

#define WD 128
#define FO 6145
#define TP 6400           // t-major padded rows
#define TFULL 8192
#define NL 20

// ---------------- scratch ----------------------------------------------------
__device__ __align__(256) float g_x0[(size_t)8 * WD * TFULL + 2048];
__device__ __align__(256) float g_x1[(size_t)8 * WD * TFULL + 2048];
__device__ __align__(256) unsigned short g_actsH[(size_t)8 * TP * 2560]; // [b][t][l*128+c]
__device__ __align__(256) unsigned short g_skipH[(size_t)8 * TP * 512];  // [b][t][o]
__device__ __align__(256) unsigned short g_hH[(size_t)8 * TP * 512];
__device__ __align__(256) unsigned g_iWd[(size_t)NL * 32768];  // fragment-packed half2
__device__ __align__(256) unsigned g_iWr[(size_t)NL * 8192];
__device__ __align__(256) unsigned g_iWs[655360];
__device__ __align__(256) unsigned g_iP1[131072];
__device__ __align__(256) unsigned g_iP2[65536];

// ---------------- helpers ----------------------------------------------------
__device__ __forceinline__ void mmaf16(float* c, uint4 a, uint2 b) {
    asm volatile("mma.sync.aligned.m16n8k16.row.col.f32.f16.f16.f32 "
                 "{%0,%1,%2,%3},{%4,%5,%6,%7},{%8,%9},{%0,%1,%2,%3};\n"
                 : "+f"(c[0]), "+f"(c[1]), "+f"(c[2]), "+f"(c[3])
                 : "r"(a.x), "r"(a.y), "r"(a.z), "r"(a.w), "r"(b.x), "r"(b.y));
}
__device__ __forceinline__ float tanh_fast(float v) {
    float t; asm("tanh.approx.f32 %0, %1;" : "=f"(t) : "f"(v)); return t;
}
__device__ __forceinline__ void cp16(uint4* dst_smem, const uint4* src) {
    unsigned a = (unsigned)__cvta_generic_to_shared(dst_smem);
    asm volatile("cp.async.cg.shared.global [%0], [%1], 16;" :: "r"(a), "l"(src));
}
#define CP_COMMIT asm volatile("cp.async.commit_group;")
#define CP_WAIT0  asm volatile("cp.async.wait_group 0;")
#define CP_WAIT1  asm volatile("cp.async.wait_group 1;")

__device__ __forceinline__ unsigned pk2(float lo, float hi) {
    __half2 h = __floats2half2_rn(lo, hi);
    return *(unsigned*)&h;
}
// swizzled B-fragment half index for element (k, t): slot gg XOR'd with tt&7
__device__ __forceinline__ int bIdx(int k, int t) {
    int ch = k >> 4, kk = k & 15, tt = t >> 3, gg = t & 7;
    int r = kk >> 3, qq = (kk & 7) >> 1, hh = kk & 1;
    return ((((ch * 16 + tt) * 32 + ((gg ^ (tt & 7)) << 2) + qq) * 2 + r) << 1) | hh;
}
__device__ __forceinline__ void stB(unsigned* Xs, int k, int t, float v) {
    ((__half*)Xs)[bIdx(k, t)] = __float2half_rn(v);
}

// ---------------- merged weight image prep (ONE launch) ----------------------
// rows 0..19: Wd (gate-permuted M); 20..39: Wr; 40: Ws; 41: p1; 42: p2
__global__ void __launch_bounds__(256) prepAll(
    const float* __restrict__ Wd, const float* __restrict__ Wr,
    const float* __restrict__ Ws, const float* __restrict__ p1,
    const float* __restrict__ p2,
    unsigned* __restrict__ iWd, unsigned* __restrict__ iWr,
    unsigned* __restrict__ iWs, unsigned* __restrict__ iP1,
    unsigned* __restrict__ iP2)
{
    int row = blockIdx.y;
    const float* W; unsigned* img; int K, NO; bool perm = false;
    if (row < 20)      { W = Wd + (size_t)row * 65536;        img = iWd + (size_t)row * 32768; K = 256;  NO = 256; perm = true; }
    else if (row < 40) { W = Wr + (size_t)(row - 20) * 16384; img = iWr + (size_t)(row - 20) * 8192; K = 128; NO = 128; }
    else if (row == 40){ W = Ws; img = iWs; K = 2560; NO = 512; }
    else if (row == 41){ W = p1; img = iP1; K = 512;  NO = 512; }
    else               { W = p2; img = iP2; K = 512;  NO = 256; }

    int OTB = (NO >= 256) ? 256 : NO;
    int mtiles = OTB / 16, chunks = K / 16;
    int total = (K * NO) >> 1;
    for (int idx = blockIdx.x * 256 + threadIdx.x; idx < total; idx += gridDim.x * 256) {
        int r = idx & 3, lane = (idx >> 2) & 31;
        int t2 = idx >> 7;
        int mt = t2 % mtiles; t2 /= mtiles;
        int ch = t2 % chunks; int ot = t2 / chunks;
        int m;
        if (perm) m = mt * 8 + (lane >> 2) + ((r & 1) << 7);   // rows 0-7 tanh c, 8-15 sigmoid c+128
        else      m = ot * OTB + mt * 16 + (lane >> 2) + ((r & 1) << 3);
        int k0 = ch * 16 + (lane & 3) * 2 + (r >> 1) * 8;
        __half2 h = __floats2half2_rn(W[(size_t)k0 * NO + m], W[(size_t)(k0 + 1) * NO + m]);
        img[idx] = *(unsigned*)&h;
    }
}

// ---------------- embedding ---------------------------------------------------
__global__ void __launch_bounds__(256) embed_kernel(
    const int* __restrict__ y, const float* __restrict__ emb, float* __restrict__ x)
{
    int b = blockIdx.y;
    int t = blockIdx.x * 32 + (threadIdx.x & 31);
    int cg = threadIdx.x >> 5;
    int idx = y[b * TFULL + t];
    const float* er = emb + (size_t)idx * WD;
    float* xb = x + (size_t)b * WD * TFULL;
#pragma unroll
    for (int j = 0; j < 16; ++j) xb[(size_t)(cg * 16 + j) * TFULL + t] = er[cg * 16 + j];
}

// weight-ring stage fill: stages 0..3 = Wd 32KB quarters; stage 4 = Wr (32KB)
__device__ __forceinline__ void issueW(
    unsigned* Wr3, const unsigned* iWdl, const unsigned* iWrl, int u, int tid)
{
    uint4* dst = (uint4*)(Wr3 + (u % 3) * 8192);
    const uint4* src = (u < 4) ? (const uint4*)(iWdl + u * 8192)
                               : (const uint4*)iWrl;
    for (int i = tid; i < 2048; i += 512) cp16(dst + i, src + i);
    CP_COMMIT;
}

// ---------------- fused per-layer kernel ------------------------------------
__global__ void __launch_bounds__(512, 1) layer_kernel(
    const float* __restrict__ xin, float* __restrict__ xout,
    const unsigned* __restrict__ iWd, const float* __restrict__ bdl,
    const unsigned* __restrict__ iWr, const float* __restrict__ brl,
    int d, int Lout, int layer)
{
    extern __shared__ unsigned sm[];
    unsigned* Xs = sm;            // 16384 u32: swizzled B-fragment tile
    unsigned* Wr3 = sm + 16384;   // 3 x 8192 u32: weight ring

    const int tid = threadIdx.x;
    const int w = tid >> 5, lane = tid & 31, g = lane >> 2, q = lane & 3;
    const int b = blockIdx.y;
    const int t0 = blockIdx.x * 128;
    const float* xb = xin + (size_t)b * WD * TFULL;
    const unsigned* iWdl = iWd + (size_t)layer * 32768;
    const unsigned* iWrl = iWr + (size_t)layer * 8192;

    issueW(Wr3, iWdl, iWrl, 0, tid);
    issueW(Wr3, iWdl, iWrl, 1, tid);

    // ---- X tile: packed k-pair stores (STS.32, swizzled)
    {
        const int npv = ((d & 3) == 0) ? 128 : 64;  // kpairs done vectorized
        for (int i = tid; i < npv * 32; i += 512) {
            int kp = i >> 5, l = i & 31;
            int t4 = l << 2;
            int k0 = kp << 1;
            int off = (k0 >= 128) ? d : 0;
            int tg = t0 + t4 + off; if (tg > TFULL - 4) tg = TFULL - 4;
            const float* p0 = xb + (size_t)(k0 & 127) * TFULL + tg;
            float4 va = *(const float4*)p0;
            float4 vb = *(const float4*)(p0 + TFULL);
            int qq = kp & 3, r = (kp >> 2) & 1, ch = kp >> 3;
            int tt = t4 >> 3, gg = t4 & 7, s = tt & 7;
            int rb = (ch * 16 + tt) * 64 + r;
            unsigned u0 = pk2(va.x, vb.x), u1 = pk2(va.y, vb.y);
            unsigned u2 = pk2(va.z, vb.z), u3 = pk2(va.w, vb.w);
            Xs[rb + ((((gg + 0) ^ s) << 2) + qq) * 2] = u0;
            Xs[rb + ((((gg + 1) ^ s) << 2) + qq) * 2] = u1;
            Xs[rb + ((((gg + 2) ^ s) << 2) + qq) * 2] = u2;
            Xs[rb + ((((gg + 3) ^ s) << 2) + qq) * 2] = u3;
        }
        if (d & 3) {   // tap1 scalar path (kp 64..127)
            for (int i = tid; i < 64 * 128; i += 512) {
                int t = i & 127, kp = 64 + (i >> 7);
                int cc = (kp << 1) & 127;
                int tg = t0 + t + d; if (tg > TFULL - 1) tg = TFULL - 1;
                const float* p0 = xb + (size_t)cc * TFULL + tg;
                float lo = p0[0], hi = p0[TFULL];
                int qq = kp & 3, r = (kp >> 2) & 1, ch = kp >> 3;
                int tt = t >> 3, gg = t & 7, s = tt & 7;
                Xs[(ch * 16 + tt) * 64 + r + (((gg ^ s) << 2) + qq) * 2] = pk2(lo, hi);
            }
        }
    }

    const int n0 = (w >> 2) * 32;
    const int mtb = (w & 3) * 4, ntb = n0 >> 3;

    float acc[4][4][4];
#pragma unroll
    for (int mf = 0; mf < 4; ++mf)
#pragma unroll
        for (int nf = 0; nf < 4; ++nf)
#pragma unroll
            for (int e = 0; e < 4; ++e) acc[mf][nf][e] = 0.0f;

    // ---- Phase 1: 4 stages of k64
    for (int u = 0; u < 4; ++u) {
        CP_WAIT1;
        __syncthreads();
        if (u + 2 <= 4) issueW(Wr3, iWdl, iWrl, u + 2, tid);
        const unsigned* Wst = Wr3 + (u % 3) * 8192;
        for (int sp = 0; sp < 2; ++sp) {
#pragma unroll
            for (int s2 = 0; s2 < 2; ++s2) {
                int sub = sp * 2 + s2;
                int chAbs = u * 4 + sub;
                const unsigned* Wc = Wst + (sub >> 1) * 4096;
                uint4 A[4]; uint2 B[4];
#pragma unroll
                for (int mf = 0; mf < 4; ++mf)
                    A[mf] = *(const uint4*)(Wc + (((sub & 1) * 16 + mtb + mf) * 32 + lane) * 4);
#pragma unroll
                for (int nf = 0; nf < 4; ++nf) {
                    int tnf = ntb + nf;
                    B[nf] = *(const uint2*)(Xs + ((chAbs * 16 + tnf) * 32 +
                                                  (lane ^ ((tnf & 7) << 2))) * 2);
                }
#pragma unroll
                for (int mf = 0; mf < 4; ++mf)
#pragma unroll
                    for (int nf = 0; nf < 4; ++nf)
                        mmaf16(acc[mf][nf], A[mf], B[nf]);
            }
        }
    }
    __syncthreads();   // all reads of Xs done before gate overwrites

    // ---- gate IN REGISTERS: acc rows 0-7 of each tile = tanh(c), rows 8-15 = sigmoid(c+128)
#pragma unroll
    for (int mf = 0; mf < 4; ++mf) {
        int c = (mtb + mf) * 8 + g;
        float b0v = bdl[c], b1v = bdl[c + 128];
#pragma unroll
        for (int nf = 0; nf < 4; ++nf) {
            int c0 = n0 + nf * 8 + q * 2;
#pragma unroll
            for (int e = 0; e < 2; ++e) {
                float vt = acc[mf][nf][e] + b0v;
                float vs = acc[mf][nf][e + 2] + b1v;
                float av = tanh_fast(vt) * __fdividef(1.0f, 1.0f + __expf(-vs));
                stB(Xs, c, c0 + e, av);
            }
        }
    }
    __syncthreads();

    // ---- acts tail: read swizzled fragment layout, permute to c-sequential
    {
        const int tail = Lout - FO;
        if (t0 + 128 > tail) {
            __half* ag = (__half*)g_actsH + (size_t)b * TP * 2560 + layer * 128;
            for (int i = tid; i < 1024; i += 512) {
                int t = i >> 3, ch = i & 7;
                int tg = t0 + t;
                if (tg >= tail && tg < Lout) {
                    int tt = t >> 3, gg = t & 7;
                    const uint4* src = (const uint4*)(Xs + (ch * 16 + tt) * 64 +
                                                      ((gg ^ (tt & 7)) << 3));
                    uint4 lo = src[0], hi = src[1];
                    uint4 o0 = make_uint4(lo.x, lo.z, hi.x, hi.z);   // c 0..7
                    uint4 o1 = make_uint4(lo.y, lo.w, hi.y, hi.w);   // c 8..15
                    *(uint4*)(ag + (size_t)(tg - tail) * 2560 + ch * 16) = o0;
                    *(uint4*)(ag + (size_t)(tg - tail) * 2560 + ch * 16 + 8) = o1;
                }
            }
        }
    }

    // ---- Phase 2: Wr fully staged (stage 4); one wait + sync
    const int mtb2 = (w & 3) * 2;
    float ac2[2][4][4];
#pragma unroll
    for (int mf = 0; mf < 2; ++mf)
#pragma unroll
        for (int nf = 0; nf < 4; ++nf)
#pragma unroll
            for (int e = 0; e < 4; ++e) ac2[mf][nf][e] = 0.0f;

    CP_WAIT0;
    __syncthreads();
    {
        const unsigned* Wst2 = Wr3 + (4 % 3) * 8192;
        for (int sp = 0; sp < 4; ++sp) {
#pragma unroll
            for (int s2 = 0; s2 < 2; ++s2) {
                int sub = sp * 2 + s2;
                const unsigned* Wc = Wst2 + (sub >> 1) * 2048;
                uint4 A[2]; uint2 B[4];
#pragma unroll
                for (int mf = 0; mf < 2; ++mf)
                    A[mf] = *(const uint4*)(Wc + (((sub & 1) * 8 + mtb2 + mf) * 32 + lane) * 4);
#pragma unroll
                for (int nf = 0; nf < 4; ++nf) {
                    int tnf = ntb + nf;
                    B[nf] = *(const uint2*)(Xs + ((sub * 16 + tnf) * 32 +
                                                  (lane ^ ((tnf & 7) << 2))) * 2);
                }
#pragma unroll
                for (int mf = 0; mf < 2; ++mf)
#pragma unroll
                    for (int nf = 0; nf < 4; ++nf)
                        mmaf16(ac2[mf][nf], A[mf], B[nf]);
            }
        }
    }
    __syncthreads();   // Xs free now; reuse as f32 Rs

    float* Rs = (float*)Xs;
    const int m0b = (w & 3) * 32;
#pragma unroll
    for (int mf = 0; mf < 2; ++mf) {
        int r0 = m0b + mf * 16 + g;
        float br0 = brl[r0], br1 = brl[r0 + 8];
#pragma unroll
        for (int nf = 0; nf < 4; ++nf) {
            int c0 = n0 + nf * 8 + q * 2;
#pragma unroll
            for (int e = 0; e < 4; ++e) {
                int row = r0 + ((e >= 2) ? 8 : 0), col = c0 + (e & 1);
                Rs[row * 128 + col] = ac2[mf][nf][e] + ((e >= 2) ? br1 : br0);
            }
        }
    }
    __syncthreads();

    float* xo = xout + (size_t)b * WD * TFULL;
    if (((d & 3) == 0) && (t0 + 128 <= Lout)) {
        for (int i = tid; i < 128 * 32; i += 512) {
            int cc = i >> 5, t4 = (i & 31) << 2;
            float4 r4 = *(float4*)(Rs + cc * 128 + t4);
            float4 x4 = *(const float4*)(xb + (size_t)cc * TFULL + t0 + t4 + d);
            float4 o;
            o.x = r4.x + x4.x; o.y = r4.y + x4.y;
            o.z = r4.z + x4.z; o.w = r4.w + x4.w;
            *(float4*)(xo + (size_t)cc * TFULL + t0 + t4) = o;
        }
    } else {
        for (int i = tid; i < 128 * 128; i += 512) {
            int cc = i >> 7, t = i & 127, tg = t0 + t;
            if (tg < Lout)
                xo[(size_t)cc * TFULL + tg] = Rs[cc * 128 + t] + xb[(size_t)cc * TFULL + tg + d];
        }
    }
}

// ---------------- fp16 GEMM (unchanged from R15) -----------------------------
__global__ void __launch_bounds__(512, 1) gemm_f16(
    const unsigned short* __restrict__ XH, const unsigned* __restrict__ imgA,
    const float* __restrict__ bias, int nbias, int doRelu,
    int K, int NO, void* __restrict__ outp, int tmajor)
{
    extern __shared__ unsigned sm[];
    unsigned* As3 = sm;            // 3 x 4096 u32
    unsigned* Bs3 = sm + 12288;    // 3 x 2048 u32

    const int tid = threadIdx.x;
    const int w = tid >> 5, lane = tid & 31, g = lane >> 2, q = lane & 3;
    const int b = blockIdx.z, ot = blockIdx.y;
    const int t0 = blockIdx.x * 128;
    const int NC = K >> 5, chunks = K >> 4;
    const __half* Xb = (const __half*)XH + (size_t)b * TP * K;
    const unsigned* imgOt = imgA + (size_t)ot * chunks * 2048;

    const int m0 = (w & 3) * 64, n0 = (w >> 2) * 32;
    const int mtb = (w & 3) * 4, ntb = n0 >> 3;

    const int bt = tid >> 2, bj = tid & 3;
    const int bsub = bj >> 1, br_ = bj & 1, btt = bt >> 3, bgg = bt & 7;
    const unsigned bbase = ((bsub * 16 + btt) * 32 + bgg * 4) * 2 + br_;

    {
        const uint4* src0 = (const uint4*)(imgOt);
        for (int i = tid; i < 1024; i += 512) cp16((uint4*)As3 + i, src0 + i);
        CP_COMMIT;
        uint4 v0 = *(const uint4*)(Xb + (size_t)(t0 + bt) * K + bj * 8);
        Bs3[bbase] = v0.x; Bs3[bbase + 2] = v0.y; Bs3[bbase + 4] = v0.z; Bs3[bbase + 6] = v0.w;
        const uint4* src1 = (const uint4*)(imgOt + 4096);
        uint4* dst1 = (uint4*)(As3 + 4096);
        for (int i = tid; i < 1024; i += 512) cp16(dst1 + i, src1 + i);
        CP_COMMIT;
        uint4 v1 = *(const uint4*)(Xb + (size_t)(t0 + bt) * K + 32 + bj * 8);
        unsigned* Bd1 = Bs3 + 2048;
        Bd1[bbase] = v1.x; Bd1[bbase + 2] = v1.y; Bd1[bbase + 4] = v1.z; Bd1[bbase + 6] = v1.w;
    }

    float acc[4][4][4];
#pragma unroll
    for (int mf = 0; mf < 4; ++mf)
#pragma unroll
        for (int nf = 0; nf < 4; ++nf)
#pragma unroll
            for (int e = 0; e < 4; ++e) acc[mf][nf][e] = 0.0f;

    for (int c = 0; c < NC; ++c) {
        if (c + 1 < NC) { CP_WAIT1; } else { CP_WAIT0; }
        __syncthreads();
        uint4 vb;
        const bool pend = (c + 2 < NC);
        if (pend) {
            const uint4* src = (const uint4*)(imgOt + (c + 2) * 4096);
            uint4* dst = (uint4*)(As3 + ((c + 2) % 3) * 4096);
            for (int i = tid; i < 1024; i += 512) cp16(dst + i, src + i);
            CP_COMMIT;
            vb = *(const uint4*)(Xb + (size_t)(t0 + bt) * K + (c + 2) * 32 + bj * 8);
        }
        const unsigned* Wst = As3 + (c % 3) * 4096;
        const unsigned* Bst = Bs3 + (c % 3) * 2048;
#pragma unroll
        for (int sub = 0; sub < 2; ++sub) {
            uint4 A[4]; uint2 B[4];
#pragma unroll
            for (int mf = 0; mf < 4; ++mf)
                A[mf] = *(const uint4*)(Wst + ((sub * 16 + mtb + mf) * 32 + lane) * 4);
#pragma unroll
            for (int nf = 0; nf < 4; ++nf)
                B[nf] = *(const uint2*)(Bst + ((sub * 16 + ntb + nf) * 32 + lane) * 2);
#pragma unroll
            for (int mf = 0; mf < 4; ++mf)
#pragma unroll
                for (int nf = 0; nf < 4; ++nf)
                    mmaf16(acc[mf][nf], A[mf], B[nf]);
        }
        if (pend) {
            unsigned* Bd = Bs3 + ((c + 2) % 3) * 2048;
            Bd[bbase] = vb.x; Bd[bbase + 2] = vb.y; Bd[bbase + 4] = vb.z; Bd[bbase + 6] = vb.w;
        }
    }

#pragma unroll
    for (int mf = 0; mf < 4; ++mf) {
        int r0 = ot * 256 + m0 + mf * 16 + g;
        float bs0 = 0.0f, bs1 = 0.0f;
        for (int i = 0; i < nbias; ++i) {
            bs0 += bias[(size_t)i * NO + r0];
            bs1 += bias[(size_t)i * NO + r0 + 8];
        }
#pragma unroll
        for (int nf = 0; nf < 4; ++nf) {
            int c0 = t0 + n0 + nf * 8 + q * 2;
#pragma unroll
            for (int e = 0; e < 4; ++e) {
                int row = r0 + ((e >= 2) ? 8 : 0);
                int t = c0 + (e & 1);
                float v = acc[mf][nf][e] + ((e >= 2) ? bs1 : bs0);
                if (doRelu) v = fmaxf(v, 0.0f);
                if (tmajor) {
                    ((__half*)outp)[((size_t)b * TP + t) * NO + row] = __float2half_rn(v);
                } else {
                    if (t < FO)
                        ((float*)outp)[((size_t)b * NO + row) * FO + t] = v;
                }
            }
        }
    }
}

// ---------------- host launcher ----------------------------------------------
extern "C" void kernel_launch(void* const* d_in, const int* in_sizes, int n_in,
                              void* d_out, int out_size)
{
    const int*   y   = (const int*)d_in[0];
    const float* emb = (const float*)d_in[1];
    const float* Wd  = (const float*)d_in[2];
    const float* bd  = (const float*)d_in[3];
    const float* Wr  = (const float*)d_in[4];
    const float* br  = (const float*)d_in[5];
    const float* Ws  = (const float*)d_in[6];
    const float* bs  = (const float*)d_in[7];
    const float* p1  = (const float*)d_in[8];
    const float* p2  = (const float*)d_in[9];
    float* out = (float*)d_out;

    static const int dil[NL] = {1, 2, 4, 8, 16, 32, 64, 128, 256, 512,
                                1, 2, 4, 8, 16, 32, 64, 128, 256, 512};

    size_t smemL = (size_t)(16384 + 3 * 8192) * 4;       // 163,840 B
    size_t smemG = (size_t)(12288 + 6144) * 4;           //  73,728 B
    cudaFuncSetAttribute(layer_kernel, cudaFuncAttributeMaxDynamicSharedMemorySize, (int)smemL);
    cudaFuncSetAttribute(gemm_f16,     cudaFuncAttributeMaxDynamicSharedMemorySize, (int)smemG);

    float *x0, *x1;
    unsigned short *actsH, *skipH, *hH;
    unsigned *iWd, *iWr, *iWs, *iP1, *iP2;
    cudaGetSymbolAddress((void**)&x0,    g_x0);
    cudaGetSymbolAddress((void**)&x1,    g_x1);
    cudaGetSymbolAddress((void**)&actsH, g_actsH);
    cudaGetSymbolAddress((void**)&skipH, g_skipH);
    cudaGetSymbolAddress((void**)&hH,    g_hH);
    cudaGetSymbolAddress((void**)&iWd,   g_iWd);
    cudaGetSymbolAddress((void**)&iWr,   g_iWr);
    cudaGetSymbolAddress((void**)&iWs,   g_iWs);
    cudaGetSymbolAddress((void**)&iP1,   g_iP1);
    cudaGetSymbolAddress((void**)&iP2,   g_iP2);

    prepAll<<<dim3(128, 43), 256>>>(Wd, Wr, Ws, p1, p2, iWd, iWr, iWs, iP1, iP2);

    embed_kernel<<<dim3(TFULL / 32, 8), 256>>>(y, emb, x0);

    float* xin = x0;
    float* xout = x1;
    int Tin = TFULL;
    for (int i = 0; i < NL; ++i) {
        int d = dil[i];
        int Lout = Tin - d;
        dim3 grid((Lout + 127) / 128, 8);
        layer_kernel<<<grid, 512, smemL>>>(
            xin, xout, iWd, bd + (size_t)i * 2 * WD, iWr, br + (size_t)i * WD,
            d, Lout, i);
        float* tmp = xin; xin = xout; xout = tmp;
        Tin = Lout;
    }

    dim3 g1(TP / 128, 2, 8);
    gemm_f16<<<g1, 512, smemG>>>(actsH, iWs, bs, NL, 1, 2560, 512, skipH, 1);
    gemm_f16<<<g1, 512, smemG>>>(skipH, iP1, nullptr, 0, 1, 512, 512, hH, 1);
    dim3 g3(TP / 128, 1, 8);
    gemm_f16<<<g3, 512, smemG>>>(hH, iP2, nullptr, 0, 0, 512, 256, out, 0);
}